// round 12
// baseline (speedup 1.0000x reference)
#include <cuda_runtime.h>
#include <cuda_bf16.h>
#include <cstdint>

// ============================================================================
// QuantizedActorMLP on mma.sync bf16 HMMA, lean register version.
// x[B,17] -> fq -> L1(17->64)+fq -> L2(64->64)+fq -> L3(64->6).
// Exact integer math in bf16-in / f32-acc MMAs; C-frag == next A-frag.
// Round 12: ONE 16-row tile per warp, per-N-pair C streaming (8 live C regs),
// natural register allocation (no forced occupancy), no constant-bank copy.
// ============================================================================

#define ACT_SCALE 1.33f
#define QMAXF     127.0f
#define MAGIC     12582912.0f      // 1.5 * 2^23

__device__ float gG[3];               // s1, s2, step*s3

// weights pre-baked in m16n8k16 B-fragment order: u32[chunk][lane][4]
__device__ uint32_t gW1f[8 * 128];    // L1: chunk = kt(2)*4 + p(4)
__device__ uint32_t gW2f[16 * 128];   // L2: chunk = kt(4)*4 + p(4)
__device__ uint32_t gW3f[2 * 128];    // L3: chunk = ktp(2)
__device__ float    gB1s[64];         // b1/step
__device__ float    gB2s[64];         // b2/step
__device__ float    gB3[8];           // b3 (cols 6,7 = 0)

#define CVT_BF16X2(res, vlo, vhi) \
    asm("cvt.rn.bf16x2.f32 %0, %1, %2;" : "=r"(res) : "f"(vhi), "f"(vlo))

#define MMA16816(Cv, Av, b0, b1)                                              \
    asm volatile(                                                             \
        "mma.sync.aligned.m16n8k16.row.col.f32.bf16.bf16.f32 "                \
        "{%0,%1,%2,%3}, {%4,%5,%6,%7}, {%8,%9}, {%0,%1,%2,%3};"               \
        : "+f"((Cv)[0]), "+f"((Cv)[1]), "+f"((Cv)[2]), "+f"((Cv)[3])          \
        : "r"((Av)[0]), "r"((Av)[1]), "r"((Av)[2]), "r"((Av)[3]),             \
          "r"(b0), "r"(b1))

__device__ __forceinline__ float quant_in(float v) {
    const float INV = QMAXF / ACT_SCALE;
    v = fminf(fmaxf(v, -ACT_SCALE), ACT_SCALE);
    float t = fmaf(v, INV, MAGIC);
    return __fadd_rn(t, -MAGIC);
}

// requant 2 accumulators -> packed int-valued bf16x2 (R5/R7-proven)
__device__ __forceinline__ uint32_t requant2(float c0, float c1, float G, float2 b) {
    float f0 = fmaf(c0, G, b.x);
    float f1 = fmaf(c1, G, b.y);
    f0 = fminf(fmaxf(f0, -QMAXF), QMAXF);
    f1 = fminf(fmaxf(f1, -QMAXF), QMAXF);
    f0 = __fadd_rn(__fadd_rn(f0, MAGIC), -MAGIC);
    f1 = __fadd_rn(__fadd_rn(f1, MAGIC), -MAGIC);
    uint32_t r; CVT_BF16X2(r, f0, f1);
    return r;
}

__device__ __forceinline__ uint16_t qweight(float w, float s) {
    float r = rintf(w / s);
    r = fminf(fmaxf(r, -QMAXF), QMAXF);
    return __bfloat16_as_ushort(__float2bfloat16(r));
}

// ============================================================================
// Prep (R5-proven): scales, quantize weights, bake into B-fragment order.
//   B reg b0 of tile (kt, nt), lane L: n = nt*8 + L/4, k0 = kt*16 + (L%4)*2,
//      b0 = bf16x2{ lo = W[n][k0], hi = W[n][k0+1] },  b1: k0+8.
// ============================================================================
__global__ void prep_kernel(const float* __restrict__ W1, const float* __restrict__ b1,
                            const float* __restrict__ W2, const float* __restrict__ b2,
                            const float* __restrict__ W3, const float* __restrict__ b3) {
    __shared__ float red[256];
    __shared__ float sS[3];
    const int tid = threadIdx.x;
    const float* Ws[3]  = {W1, W2, W3};
    const int    nel[3] = {64 * 17, 64 * 64, 6 * 64};

    for (int t = 0; t < 3; ++t) {
        float m = 0.0f;
        for (int i = tid; i < nel[t]; i += 256) m = fmaxf(m, fabsf(Ws[t][i]));
        red[tid] = m; __syncthreads();
        for (int s = 128; s > 0; s >>= 1) {
            if (tid < s) red[tid] = fmaxf(red[tid], red[tid + s]);
            __syncthreads();
        }
        if (tid == 0) sS[t] = red[0] / QMAXF;
        __syncthreads();
    }
    const float s1 = sS[0], s2 = sS[1], s3 = sS[2];
    const float step = ACT_SCALE / QMAXF;
    if (tid == 0) { gG[0] = s1; gG[1] = s2; gG[2] = step * s3; }
    if (tid < 64) {
        gB1s[tid] = b1[tid] / step;
        gB2s[tid] = b2[tid] / step;
    }
    if (tid < 8) gB3[tid] = (tid < 6) ? b3[tid] : 0.0f;

    for (int idx = tid; idx < 8 * 128; idx += 256) {
        int c = idx >> 7, rem = idx & 127;
        int lane = rem >> 2, j = rem & 3;
        int kt = c >> 2, ntp = c & 3;
        int nt = ntp * 2 + (j >> 1), jj = j & 1;
        int n  = nt * 8 + (lane >> 2);
        int k0 = kt * 16 + (lane & 3) * 2 + jj * 8;
        uint16_t lo = (k0     < 17) ? qweight(W1[n * 17 + k0],     s1) : (uint16_t)0;
        uint16_t hi = (k0 + 1 < 17) ? qweight(W1[n * 17 + k0 + 1], s1) : (uint16_t)0;
        gW1f[idx] = (uint32_t)lo | ((uint32_t)hi << 16);
    }
    for (int idx = tid; idx < 16 * 128; idx += 256) {
        int c = idx >> 7, rem = idx & 127;
        int lane = rem >> 2, j = rem & 3;
        int kt = c >> 2, ntp = c & 3;
        int nt = ntp * 2 + (j >> 1), jj = j & 1;
        int n  = nt * 8 + (lane >> 2);
        int k0 = kt * 16 + (lane & 3) * 2 + jj * 8;
        uint16_t lo = qweight(W2[(n << 6) + k0],     s2);
        uint16_t hi = qweight(W2[(n << 6) + k0 + 1], s2);
        gW2f[idx] = (uint32_t)lo | ((uint32_t)hi << 16);
    }
    for (int idx = tid; idx < 2 * 128; idx += 256) {
        int c = idx >> 7, rem = idx & 127;
        int lane = rem >> 2, j = rem & 3;
        int kt = c * 2 + (j >> 1), jj = j & 1;
        int n  = lane >> 2;
        int k0 = kt * 16 + (lane & 3) * 2 + jj * 8;
        uint16_t lo = (n < 6) ? qweight(W3[(n << 6) + k0],     s3) : (uint16_t)0;
        uint16_t hi = (n < 6) ? qweight(W3[(n << 6) + k0 + 1], s3) : (uint16_t)0;
        gW3f[idx] = (uint32_t)lo | ((uint32_t)hi << 16);
    }
}

// ============================================================================
// Main kernel: 256 threads = 8 warps, one 16-row tile per warp (128 rows/CTA).
// Per-N-pair C streaming keeps live registers low.
// ============================================================================
__global__ __launch_bounds__(256) void mlp_kernel(
    const float* __restrict__ x, float* __restrict__ out, int B) {

    __shared__ float    sx[128 * 18];
    __shared__ uint32_t sW1[8 * 128];
    __shared__ uint32_t sW2[16 * 128];
    __shared__ uint32_t sW3[2 * 128];
    __shared__ float    sb1[64], sb2[64], sb3[8];

    const int tid  = threadIdx.x;
    const int warp = tid >> 5;
    const int lane = tid & 31;
    const int g    = lane >> 2;
    const int t    = lane & 3;
    const int rowbase = blockIdx.x * 128;

    // ---- stage weights + biases + input tile ----
    for (int i = tid; i < 8 * 128;  i += 256) sW1[i] = gW1f[i];
    for (int i = tid; i < 16 * 128; i += 256) sW2[i] = gW2f[i];
    sW3[tid] = gW3f[tid];
    if (tid < 64) { sb1[tid] = gB1s[tid]; sb2[tid] = gB2s[tid]; }
    if (tid < 8)  sb3[tid] = gB3[tid];

    for (int i = tid; i < 128 * 17; i += 256) {
        int r = i / 17, k = i - r * 17;
        int gr = rowbase + r;
        sx[r * 18 + k] = (gr < B) ? x[(size_t)gr * 17 + k] : 0.0f;
    }
    __syncthreads();

    const float G1 = __ldg(&gG[0]);
    const float G2 = __ldg(&gG[1]);
    const float G3 = __ldg(&gG[2]);

    const int r0 = warp * 16 + g;
    const int r1 = r0 + 8;

    // ---- input A fragments (K = 32, cols >= 17 zero) — R5-proven ----
    uint32_t A1[2][4];
    {
        const float* x0 = sx + r0 * 18;
        const float* x1 = sx + r1 * 18;
        float q00 = quant_in(x0[2 * t]),      q01 = quant_in(x0[2 * t + 1]);
        float q10 = quant_in(x1[2 * t]),      q11 = quant_in(x1[2 * t + 1]);
        float q02 = quant_in(x0[2 * t + 8]),  q03 = quant_in(x0[2 * t + 9]);
        float q12 = quant_in(x1[2 * t + 8]),  q13 = quant_in(x1[2 * t + 9]);
        CVT_BF16X2(A1[0][0], q00, q01);
        CVT_BF16X2(A1[0][1], q10, q11);
        CVT_BF16X2(A1[0][2], q02, q03);
        CVT_BF16X2(A1[0][3], q12, q13);
        if (t == 0) {
            float qa = quant_in(x0[16]);
            float qb = quant_in(x1[16]);
            CVT_BF16X2(A1[1][0], qa, 0.0f);
            CVT_BF16X2(A1[1][1], qb, 0.0f);
        } else {
            A1[1][0] = 0u; A1[1][1] = 0u;
        }
        A1[1][2] = 0u; A1[1][3] = 0u;
    }

    const float2* sb1v = (const float2*)sb1;   // pair index nt*4 + t
    const float2* sb2v = (const float2*)sb2;

    // ---- layer 1: per N-pair p, stream C (8 live floats) ----
    uint32_t A2[4][4];
#pragma unroll
    for (int p = 0; p < 4; ++p) {
        float C[2][4] = {{0, 0, 0, 0}, {0, 0, 0, 0}};
#pragma unroll
        for (int kt = 0; kt < 2; ++kt) {
            uint4 w = *(const uint4*)&sW1[((kt * 4 + p) << 7) + (lane << 2)];
            MMA16816(C[0], A1[kt], w.x, w.y);
            MMA16816(C[1], A1[kt], w.z, w.w);
        }
        const float2 bA = sb1v[(2 * p) * 4 + t];
        const float2 bB = sb1v[(2 * p + 1) * 4 + t];
        A2[p][0] = requant2(C[0][0], C[0][1], G1, bA);
        A2[p][1] = requant2(C[0][2], C[0][3], G1, bA);
        A2[p][2] = requant2(C[1][0], C[1][1], G1, bB);
        A2[p][3] = requant2(C[1][2], C[1][3], G1, bB);
    }

    // ---- layer 2: per N-pair p, kt 0..3 ----
    uint32_t A3[4][4];
#pragma unroll
    for (int p = 0; p < 4; ++p) {
        float C[2][4] = {{0, 0, 0, 0}, {0, 0, 0, 0}};
#pragma unroll
        for (int kt = 0; kt < 4; ++kt) {
            uint4 w = *(const uint4*)&sW2[((kt * 4 + p) << 7) + (lane << 2)];
            MMA16816(C[0], A2[kt], w.x, w.y);
            MMA16816(C[1], A2[kt], w.z, w.w);
        }
        const float2 bA = sb2v[(2 * p) * 4 + t];
        const float2 bB = sb2v[(2 * p + 1) * 4 + t];
        A3[p][0] = requant2(C[0][0], C[0][1], G2, bA);
        A3[p][1] = requant2(C[0][2], C[0][3], G2, bA);
        A3[p][2] = requant2(C[1][0], C[1][1], G2, bB);
        A3[p][3] = requant2(C[1][2], C[1][3], G2, bB);
    }

    // ---- layer 3: single N-tile, kt 0..3 ----
    float D[4] = {0.0f, 0.0f, 0.0f, 0.0f};
#pragma unroll
    for (int p = 0; p < 2; ++p) {
        uint4 w = *(const uint4*)&sW3[(p << 7) + (lane << 2)];
        MMA16816(D, A3[2 * p],     w.x, w.y);
        MMA16816(D, A3[2 * p + 1], w.z, w.w);
    }

    // ---- epilogue: out[row, 2t..2t+1] (t < 3) — R5-proven ----
    if (t < 3) {
        const float2 b3p = *(const float2*)&sb3[2 * t];
        const int gr0 = rowbase + r0;
        const int gr1 = rowbase + r1;
        if (gr0 < B) {
            float2 o;
            o.x = fmaf(D[0], G3, b3p.x);
            o.y = fmaf(D[1], G3, b3p.y);
            *(float2*)&out[(size_t)gr0 * 6 + 2 * t] = o;
        }
        if (gr1 < B) {
            float2 o;
            o.x = fmaf(D[2], G3, b3p.x);
            o.y = fmaf(D[3], G3, b3p.y);
            *(float2*)&out[(size_t)gr1 * 6 + 2 * t] = o;
        }
    }
}

extern "C" void kernel_launch(void* const* d_in, const int* in_sizes, int n_in,
                              void* d_out, int out_size) {
    const float* x  = (const float*)d_in[0];
    const float* W1 = (const float*)d_in[1];
    const float* b1 = (const float*)d_in[2];
    const float* W2 = (const float*)d_in[3];
    const float* b2 = (const float*)d_in[4];
    const float* W3 = (const float*)d_in[5];
    const float* b3 = (const float*)d_in[6];
    float* out = (float*)d_out;

    const int B = in_sizes[0] / 17;
    const int blocks = (B + 127) / 128;

    prep_kernel<<<1, 256>>>(W1, b1, W2, b2, W3, b3);
    mlp_kernel<<<blocks, 256>>>(x, out, B);
}

// round 13
// speedup vs baseline: 1.0757x; 1.0757x over previous
#include <cuda_runtime.h>
#include <cstdint>

// ============================================================================
// QuantizedActorMLP on mma.sync int8 IMMA (m16n8k32.s8.s8.s32, sm_80+ path).
// x[B,17] -> fq -> L1(17->64)+fq -> L2(64->64)+fq -> L3(64->6).
// All dots are exact int8 x int8 -> s32. Layer outputs are permuted at prep
// time so the s32 C-fragment requants + PRMT-packs directly into the next
// layer's s8 A-fragment — no shuffles, no smem between layers.
// Permutation: physical slot (nt, t, j) holds logical neuron
//   l = 16*(nt>>1) + 4*t + 2*(nt&1) + j   (self-arranging: l lands at k=l)
// ============================================================================

#define ACT_SCALE 1.33f
#define QMAXF     127.0f
#define MAGIC     12582912.0f   // 1.5 * 2^23

__device__ float gG[3];               // s1, s2, step*s3

// B fragments, packed s8x4 per u32, chunk layout u32[chunk][lane][4]:
//  W1: chunk m(0..3) = nt pair (2m,2m+1): (b0 nt2m, b1 nt2m, b0 nt2m+1, b1 nt2m+1)
//  W2: chunk c = kt*4 + m (kt 0..1)
//  W3: single chunk: (b0 kt0, b1 kt0, b0 kt1, b1 kt1), n natural (rows>=6 zero)
__device__ uint32_t gW1f[4 * 128];
__device__ uint32_t gW2f[8 * 128];
__device__ uint32_t gW3f[128];
__device__ float    gB1p[64];         // b1/step, permuted: [nt][t][j]
__device__ float    gB2p[64];         // b2/step, permuted
__device__ float    gB3[8];           // natural (cols 6,7 = 0)

#define IMMA16832(Cv, Av, b0, b1)                                             \
    asm volatile(                                                             \
        "mma.sync.aligned.m16n8k32.row.col.s32.s8.s8.s32 "                    \
        "{%0,%1,%2,%3}, {%4,%5,%6,%7}, {%8,%9}, {%0,%1,%2,%3};"               \
        : "+r"((Cv)[0]), "+r"((Cv)[1]), "+r"((Cv)[2]), "+r"((Cv)[3])          \
        : "r"((Av)[0]), "r"((Av)[1]), "r"((Av)[2]), "r"((Av)[3]),             \
          "r"(b0), "r"(b1))

// requant one s32 accumulator -> word whose LOW BYTE is the int8 value
// (== clamp(round_rne(acc*G + b), -127, 127); proven in R10/R11)
__device__ __forceinline__ int requant_magic(int acc, float G, float b) {
    float f = fmaf((float)acc, G, b);
    f = fminf(f, QMAXF);
    f = fmaxf(f, -QMAXF);
    return __float_as_int(__fadd_rn(f, MAGIC));
}

__device__ __forceinline__ int qw_s8(float w, float s) {
    float r = rintf(w / s);
    r = fminf(fmaxf(r, -QMAXF), QMAXF);
    return ((int)r) & 0xFF;
}

// output permutation: logical neuron at physical (nt, n_in_tile)
__device__ __forceinline__ int permN(int nt, int n) {
    return 16 * (nt >> 1) + 4 * (n >> 1) + 2 * (nt & 1) + (n & 1);
}

// ============================================================================
// Prep: scales, quantize weights, bake into permuted B-fragment order.
// B-frag (m16n8k32): b0 = bytes W[n][kt*32 + 4t + 0..3], b1 = +16; n = lane>>2.
// ============================================================================
__global__ void prep_kernel(const float* __restrict__ W1, const float* __restrict__ b1,
                            const float* __restrict__ W2, const float* __restrict__ b2,
                            const float* __restrict__ W3, const float* __restrict__ b3) {
    __shared__ float red[256];
    __shared__ float sS[3];
    const int tid = threadIdx.x;
    const float* Ws[3]  = {W1, W2, W3};
    const int    nel[3] = {64 * 17, 64 * 64, 6 * 64};

    for (int t = 0; t < 3; ++t) {
        float m = 0.0f;
        for (int i = tid; i < nel[t]; i += 256) m = fmaxf(m, fabsf(Ws[t][i]));
        red[tid] = m; __syncthreads();
        for (int s = 128; s > 0; s >>= 1) {
            if (tid < s) red[tid] = fmaxf(red[tid], red[tid + s]);
            __syncthreads();
        }
        if (tid == 0) sS[t] = red[0] / QMAXF;
        __syncthreads();
    }
    const float s1 = sS[0], s2 = sS[1], s3 = sS[2];
    const float step = ACT_SCALE / QMAXF;
    if (tid == 0) { gG[0] = s1; gG[1] = s2; gG[2] = step * s3; }

    // permuted biases: index i = nt*8 + t*2 + j -> logical l
    if (tid < 64) {
        int nt = tid >> 3, t = (tid >> 1) & 3, j = tid & 1;
        int l = 16 * (nt >> 1) + 4 * t + 2 * (nt & 1) + j;
        gB1p[tid] = b1[l] / step;
        gB2p[tid] = b2[l] / step;
    }
    if (tid < 8) gB3[tid] = (tid < 6) ? b3[tid] : 0.0f;

    // W1 frags (kt = 0 only, K padded 17 -> 32)
    for (int idx = tid; idx < 4 * 128; idx += 256) {
        int m = idx >> 7, rem = idx & 127;
        int lane = rem >> 2, slot = rem & 3;
        int g = lane >> 2, t = lane & 3;
        int nt = 2 * m + (slot >> 1);
        int half = slot & 1;
        int n = permN(nt, g);
        int k0 = half * 16 + 4 * t;
        uint32_t word = 0;
#pragma unroll
        for (int i = 0; i < 4; ++i) {
            int k = k0 + i;
            int v = (k < 17) ? qw_s8(W1[n * 17 + k], s1) : 0;
            word |= (uint32_t)v << (8 * i);
        }
        gW1f[idx] = word;
    }
    // W2 frags (kt 0..1)
    for (int idx = tid; idx < 8 * 128; idx += 256) {
        int c = idx >> 7, rem = idx & 127;
        int lane = rem >> 2, slot = rem & 3;
        int g = lane >> 2, t = lane & 3;
        int kt = c >> 2, m = c & 3;
        int nt = 2 * m + (slot >> 1);
        int half = slot & 1;
        int n = permN(nt, g);
        int k0 = kt * 32 + half * 16 + 4 * t;
        uint32_t word = 0;
#pragma unroll
        for (int i = 0; i < 4; ++i)
            word |= (uint32_t)qw_s8(W2[(n << 6) + k0 + i], s2) << (8 * i);
        gW2f[idx] = word;
    }
    // W3 frags: natural n (= g), rows >= 6 zero; slot: kt = slot>>1, half = slot&1
    for (int idx = tid; idx < 128; idx += 256) {
        int lane = idx >> 2, slot = idx & 3;
        int g = lane >> 2, t = lane & 3;
        int kt = slot >> 1, half = slot & 1;
        int k0 = kt * 32 + half * 16 + 4 * t;
        uint32_t word = 0;
        if (g < 6) {
#pragma unroll
            for (int i = 0; i < 4; ++i)
                word |= (uint32_t)qw_s8(W3[(g << 6) + k0 + i], s3) << (8 * i);
        }
        gW3f[idx] = word;
    }
}

// ============================================================================
// Main kernel: 256 threads = 8 warps, one 16-row tile per warp (128 rows/CTA).
// ============================================================================
__global__ __launch_bounds__(256) void mlp_kernel(
    const float* __restrict__ x, float* __restrict__ out, int B) {

    __shared__ __align__(16) unsigned char sxq[128 * 32];  // packed rows, pad 32
    __shared__ uint32_t sW1[4 * 128];
    __shared__ uint32_t sW2[8 * 128];
    __shared__ uint32_t sW3[128];
    __shared__ float    sb1[64], sb2[64], sb3[8];

    const int tid  = threadIdx.x;
    const int warp = tid >> 5;
    const int lane = tid & 31;
    const int g    = lane >> 2;
    const int t    = lane & 3;
    const int rowbase = blockIdx.x * 128;
    const int rows = min(128, B - rowbase);

    // ---- stage weights + biases ----
    for (int i = tid; i < 4 * 128; i += 256) sW1[i] = gW1f[i];
    for (int i = tid; i < 8 * 128; i += 256) sW2[i] = gW2f[i];
    if (tid < 128) sW3[tid] = gW3f[tid];
    if (tid < 64) { sb1[tid] = gB1p[tid]; sb2[tid] = gB2p[tid]; }
    if (tid < 8)  sb3[tid] = gB3[tid];

    // ---- zero + quantize input tile into packed bytes (rows padded to 32) ----
    const float INV = QMAXF / ACT_SCALE;
    for (int i = tid; i < 1024; i += 256) ((uint32_t*)sxq)[i] = 0u;
    __syncthreads();
    {
        const float* xg = x + (size_t)rowbase * 17;
        const int n = rows * 17;
        for (int i = tid; i < n; i += 256) {
            float v = xg[i];
            v = fminf(fmaxf(v, -ACT_SCALE), ACT_SCALE);
            float q = fmaf(v, INV, MAGIC);          // RNE round; low byte = int8
            int r = i / 17;
            int k = i - r * 17;
            sxq[r * 32 + k] = (unsigned char)__float_as_int(q);
        }
    }
    __syncthreads();

    const float G1 = __ldg(&gG[0]);
    const float G2 = __ldg(&gG[1]);
    const float G3 = __ldg(&gG[2]);

    const int r0 = warp * 16 + g;

    // ---- A1 fragments: 4 aligned LDS.32 straight from packed rows ----
    uint32_t A1[4];
    {
        const unsigned char* p0 = sxq + r0 * 32;
        const unsigned char* p1 = sxq + (r0 + 8) * 32;
        A1[0] = *(const uint32_t*)(p0 + 4 * t);
        A1[1] = *(const uint32_t*)(p1 + 4 * t);
        A1[2] = *(const uint32_t*)(p0 + 16 + 4 * t);
        A1[3] = *(const uint32_t*)(p1 + 16 + 4 * t);
    }

    const float2* sb1v = (const float2*)sb1;   // float2 index = nt*4 + t
    const float2* sb2v = (const float2*)sb2;

    // ---- layer 1: per nt-pair m, 2 MMAs, requant -> A2 (zero-shuffle pack) ----
    uint32_t A2[8];
#pragma unroll
    for (int m = 0; m < 4; ++m) {
        int C[2][4] = {{0, 0, 0, 0}, {0, 0, 0, 0}};
        uint4 w = *(const uint4*)&sW1[(m << 7) + (lane << 2)];
        IMMA16832(C[0], A1, w.x, w.y);
        IMMA16832(C[1], A1, w.z, w.w);
        const float2 bA = sb1v[(2 * m) * 4 + t];       // nt = 2m
        const float2 bB = sb1v[(2 * m + 1) * 4 + t];   // nt = 2m+1
        int pl0 = __byte_perm(requant_magic(C[0][0], G1, bA.x),
                              requant_magic(C[0][1], G1, bA.y), 0x0040);
        int ph0 = __byte_perm(requant_magic(C[0][2], G1, bA.x),
                              requant_magic(C[0][3], G1, bA.y), 0x0040);
        int pl1 = __byte_perm(requant_magic(C[1][0], G1, bB.x),
                              requant_magic(C[1][1], G1, bB.y), 0x0040);
        int ph1 = __byte_perm(requant_magic(C[1][2], G1, bB.x),
                              requant_magic(C[1][3], G1, bB.y), 0x0040);
        A2[2 * m]     = __byte_perm(pl0, pl1, 0x5410);  // rows g
        A2[2 * m + 1] = __byte_perm(ph0, ph1, 0x5410);  // rows g+8
    }

    // ---- layer 2: per nt-pair m, kt 0..1, requant -> A3 ----
    uint32_t A3[8];
#pragma unroll
    for (int m = 0; m < 4; ++m) {
        int C[2][4] = {{0, 0, 0, 0}, {0, 0, 0, 0}};
#pragma unroll
        for (int kt = 0; kt < 2; ++kt) {
            uint4 w = *(const uint4*)&sW2[((kt * 4 + m) << 7) + (lane << 2)];
            IMMA16832(C[0], (A2 + 4 * kt), w.x, w.y);
            IMMA16832(C[1], (A2 + 4 * kt), w.z, w.w);
        }
        const float2 bA = sb2v[(2 * m) * 4 + t];
        const float2 bB = sb2v[(2 * m + 1) * 4 + t];
        int pl0 = __byte_perm(requant_magic(C[0][0], G2, bA.x),
                              requant_magic(C[0][1], G2, bA.y), 0x0040);
        int ph0 = __byte_perm(requant_magic(C[0][2], G2, bA.x),
                              requant_magic(C[0][3], G2, bA.y), 0x0040);
        int pl1 = __byte_perm(requant_magic(C[1][0], G2, bB.x),
                              requant_magic(C[1][1], G2, bB.y), 0x0040);
        int ph1 = __byte_perm(requant_magic(C[1][2], G2, bB.x),
                              requant_magic(C[1][3], G2, bB.y), 0x0040);
        A3[2 * m]     = __byte_perm(pl0, pl1, 0x5410);
        A3[2 * m + 1] = __byte_perm(ph0, ph1, 0x5410);
    }

    // ---- layer 3: single N-tile, kt 0..1 ----
    int D[4] = {0, 0, 0, 0};
    {
        uint4 w = *(const uint4*)&sW3[lane << 2];
        IMMA16832(D, (A3 + 0), w.x, w.y);
        IMMA16832(D, (A3 + 4), w.z, w.w);
    }

    // ---- epilogue: out[row, 2t..2t+1] (t < 3), natural col order ----
    if (t < 3) {
        const float2 b3p = *(const float2*)&sb3[2 * t];
        const int gr0 = rowbase + r0;
        const int gr1 = gr0 + 8;
        if (gr0 < B) {
            float2 o;
            o.x = fmaf((float)D[0], G3, b3p.x);
            o.y = fmaf((float)D[1], G3, b3p.y);
            *(float2*)&out[(size_t)gr0 * 6 + 2 * t] = o;
        }
        if (gr1 < B) {
            float2 o;
            o.x = fmaf((float)D[2], G3, b3p.x);
            o.y = fmaf((float)D[3], G3, b3p.y);
            *(float2*)&out[(size_t)gr1 * 6 + 2 * t] = o;
        }
    }
}

extern "C" void kernel_launch(void* const* d_in, const int* in_sizes, int n_in,
                              void* d_out, int out_size) {
    const float* x  = (const float*)d_in[0];
    const float* W1 = (const float*)d_in[1];
    const float* b1 = (const float*)d_in[2];
    const float* W2 = (const float*)d_in[3];
    const float* b2 = (const float*)d_in[4];
    const float* W3 = (const float*)d_in[5];
    const float* b3 = (const float*)d_in[6];
    float* out = (float*)d_out;

    const int B = in_sizes[0] / 17;
    const int blocks = (B + 127) / 128;

    prep_kernel<<<1, 256>>>(W1, b1, W2, b2, W3, b3);
    mlp_kernel<<<blocks, 256>>>(x, out, B);
}

// round 14
// speedup vs baseline: 1.1393x; 1.0591x over previous
#include <cuda_runtime.h>
#include <cstdint>

// ============================================================================
// QuantizedActorMLP hybrid: 2/3 of rows on int8 IMMA tensor path (R13-proven),
// 1/3 on the DP4A scalar path (R2-proven). The two paths saturate disjoint
// pipes (tensor vs issue/fma), so co-scheduling them nearly doubles throughput.
// Block pattern period 5 = [I(128) I(128) I(128) I(128) D(256)] over 768 rows.
// ============================================================================

#define ACT_SCALE 1.33f
#define QMAXF     127.0f
#define MAGIC     12582912.0f   // 1.5 * 2^23

// -------------------- DP4A-path constants (R2 layout) --------------------
struct QConst {
    int   W1[64 * 5];    // [j][g] (K padded 17->20)
    int   W2[64 * 16];   // [j][g]
    int   W3[6 * 16];    // [k][g]
    float b1s[64];       // b1/step
    float b2s[64];       // b2/step
    float b3[8];
    float G1, G2, G3;    // s1, s2, step*s3
};
__device__   QConst gQ;
__constant__ QConst cQ;

// -------------------- IMMA-path globals (R13 layout) --------------------
__device__ float    gG[3];
__device__ uint32_t gW1f[4 * 128];
__device__ uint32_t gW2f[8 * 128];
__device__ uint32_t gW3f[128];
__device__ float    gB1p[64];
__device__ float    gB2p[64];
__device__ float    gB3[8];

__device__ __forceinline__ int packq(int q0, int q1, int q2, int q3) {
    return __byte_perm(__byte_perm(q0, q1, 0x0040),
                       __byte_perm(q2, q3, 0x0040), 0x5410);
}

#define IMMA16832(Cv, Av, b0, b1)                                             \
    asm volatile(                                                             \
        "mma.sync.aligned.m16n8k32.row.col.s32.s8.s8.s32 "                    \
        "{%0,%1,%2,%3}, {%4,%5,%6,%7}, {%8,%9}, {%0,%1,%2,%3};"               \
        : "+r"((Cv)[0]), "+r"((Cv)[1]), "+r"((Cv)[2]), "+r"((Cv)[3])          \
        : "r"((Av)[0]), "r"((Av)[1]), "r"((Av)[2]), "r"((Av)[3]),             \
          "r"(b0), "r"(b1))

// low byte = int8( clamp(round_rne(acc*G + b), -127, 127) )  (R10-proven)
__device__ __forceinline__ int requant_magic(int acc, float G, float b) {
    float f = fmaf((float)acc, G, b);
    f = fminf(f, QMAXF);
    f = fmaxf(f, -QMAXF);
    return __float_as_int(__fadd_rn(f, MAGIC));
}

__device__ __forceinline__ int qw_s8(float w, float s) {
    float r = rintf(w / s);
    r = fminf(fmaxf(r, -QMAXF), QMAXF);
    return ((int)r) & 0xFF;
}

__device__ __forceinline__ int permN(int nt, int n) {
    return 16 * (nt >> 1) + 4 * (n >> 1) + 2 * (nt & 1) + (n & 1);
}

// ============================================================================
// Prep: scales, quantize weights; bake BOTH the dp4a pack and IMMA fragments.
// ============================================================================
__global__ void prep_kernel(const float* __restrict__ W1, const float* __restrict__ b1,
                            const float* __restrict__ W2, const float* __restrict__ b2,
                            const float* __restrict__ W3, const float* __restrict__ b3) {
    __shared__ float red[256];
    __shared__ float sS[3];
    const int tid = threadIdx.x;
    const float* Ws[3]  = {W1, W2, W3};
    const int    nel[3] = {64 * 17, 64 * 64, 6 * 64};

    for (int t = 0; t < 3; ++t) {
        float m = 0.0f;
        for (int i = tid; i < nel[t]; i += 256) m = fmaxf(m, fabsf(Ws[t][i]));
        red[tid] = m; __syncthreads();
        for (int s = 128; s > 0; s >>= 1) {
            if (tid < s) red[tid] = fmaxf(red[tid], red[tid + s]);
            __syncthreads();
        }
        if (tid == 0) sS[t] = red[0] / QMAXF;
        __syncthreads();
    }
    const float s1 = sS[0], s2 = sS[1], s3 = sS[2];
    const float step = ACT_SCALE / QMAXF;
    if (tid == 0) {
        gQ.G1 = s1; gQ.G2 = s2; gQ.G3 = step * s3;
        gG[0] = s1; gG[1] = s2; gG[2] = step * s3;
    }
    if (tid < 64) {
        gQ.b1s[tid] = b1[tid] / step;
        gQ.b2s[tid] = b2[tid] / step;
        int nt = tid >> 3, t = (tid >> 1) & 3, j = tid & 1;
        int l = 16 * (nt >> 1) + 4 * t + 2 * (nt & 1) + j;
        gB1p[tid] = b1[l] / step;
        gB2p[tid] = b2[l] / step;
    }
    if (tid < 8) {
        float v = (tid < 6) ? b3[tid] : 0.0f;
        gQ.b3[tid] = v; gB3[tid] = v;
    }

    // ---- dp4a pack (R2) ----
    for (int w = tid; w < 64 * 5; w += 256) {
        int j = w / 5, g = w % 5;
        int q[4];
#pragma unroll
        for (int b = 0; b < 4; ++b) {
            int k = 4 * g + b;
            int v = 0;
            if (k < 17) {
                float r = rintf(W1[j * 17 + k] / s1);
                v = (int)fminf(fmaxf(r, -QMAXF), QMAXF);
            }
            q[b] = v;
        }
        gQ.W1[w] = packq(q[0], q[1], q[2], q[3]);
    }
    for (int w = tid; w < 64 * 16; w += 256) {
        int j = w / 16, g = w % 16;
        int q[4];
#pragma unroll
        for (int b = 0; b < 4; ++b) {
            float r = rintf(W2[j * 64 + 4 * g + b] / s2);
            q[b] = (int)fminf(fmaxf(r, -QMAXF), QMAXF);
        }
        gQ.W2[w] = packq(q[0], q[1], q[2], q[3]);
    }
    for (int w = tid; w < 6 * 16; w += 256) {
        int k = w / 16, g = w % 16;
        int q[4];
#pragma unroll
        for (int b = 0; b < 4; ++b) {
            float r = rintf(W3[k * 64 + 4 * g + b] / s3);
            q[b] = (int)fminf(fmaxf(r, -QMAXF), QMAXF);
        }
        gQ.W3[w] = packq(q[0], q[1], q[2], q[3]);
    }

    // ---- IMMA fragments (R13) ----
    for (int idx = tid; idx < 4 * 128; idx += 256) {
        int m = idx >> 7, rem = idx & 127;
        int lane = rem >> 2, slot = rem & 3;
        int g = lane >> 2, t = lane & 3;
        int nt = 2 * m + (slot >> 1);
        int half = slot & 1;
        int n = permN(nt, g);
        int k0 = half * 16 + 4 * t;
        uint32_t word = 0;
#pragma unroll
        for (int i = 0; i < 4; ++i) {
            int k = k0 + i;
            int v = (k < 17) ? qw_s8(W1[n * 17 + k], s1) : 0;
            word |= (uint32_t)v << (8 * i);
        }
        gW1f[idx] = word;
    }
    for (int idx = tid; idx < 8 * 128; idx += 256) {
        int c = idx >> 7, rem = idx & 127;
        int lane = rem >> 2, slot = rem & 3;
        int g = lane >> 2, t = lane & 3;
        int kt = c >> 2, m = c & 3;
        int nt = 2 * m + (slot >> 1);
        int half = slot & 1;
        int n = permN(nt, g);
        int k0 = kt * 32 + half * 16 + 4 * t;
        uint32_t word = 0;
#pragma unroll
        for (int i = 0; i < 4; ++i)
            word |= (uint32_t)qw_s8(W2[(n << 6) + k0 + i], s2) << (8 * i);
        gW2f[idx] = word;
    }
    for (int idx = tid; idx < 128; idx += 256) {
        int lane = idx >> 2, slot = idx & 3;
        int g = lane >> 2, t = lane & 3;
        int kt = slot >> 1, half = slot & 1;
        int k0 = kt * 32 + half * 16 + 4 * t;
        uint32_t word = 0;
        if (g < 6) {
#pragma unroll
            for (int i = 0; i < 4; ++i)
                word |= (uint32_t)qw_s8(W3[(g << 6) + k0 + i], s3) << (8 * i);
        }
        gW3f[idx] = word;
    }
}

// ============================================================================
// Hybrid kernel. Pattern period 5 blocks = 768 rows:
//   pat 0..3 -> IMMA path, 128 rows each; pat 4 -> DP4A path, 256 rows.
// ============================================================================
__global__ __launch_bounds__(256) void mlp_hybrid(
    const float* __restrict__ x, float* __restrict__ out, int B) {

    // IMMA-path smem
    __shared__ __align__(16) unsigned char s_iq[128 * 32];
    __shared__ uint32_t sW1[4 * 128];
    __shared__ uint32_t sW2[8 * 128];
    __shared__ uint32_t sW3[128];
    __shared__ float    sb1[64], sb2[64], sb3[8];
    // DP4A-path smem
    __shared__ __align__(16) unsigned char s_dq[256 * 20];
    __shared__ __align__(16) float s_out[256 * 6];

    const int tid = threadIdx.x;
    const int pat = blockIdx.x % 5;
    const int grp = blockIdx.x / 5;
    const float INV = QMAXF / ACT_SCALE;

    if (pat < 4) {
        // ================= IMMA path (R13-proven) =================
        const int rowbase = grp * 768 + pat * 128;
        if (rowbase >= B) return;
        const int rows = min(128, B - rowbase);

        const int warp = tid >> 5;
        const int lane = tid & 31;
        const int g    = lane >> 2;
        const int t    = lane & 3;

        for (int i = tid; i < 4 * 128; i += 256) sW1[i] = gW1f[i];
        for (int i = tid; i < 8 * 128; i += 256) sW2[i] = gW2f[i];
        if (tid < 128) sW3[tid] = gW3f[tid];
        if (tid < 64) { sb1[tid] = gB1p[tid]; sb2[tid] = gB2p[tid]; }
        if (tid < 8)  sb3[tid] = gB3[tid];

        for (int i = tid; i < 1024; i += 256) ((uint32_t*)s_iq)[i] = 0u;
        __syncthreads();
        {
            const float* xg = x + (size_t)rowbase * 17;
            const int n = rows * 17;
            for (int i = tid; i < n; i += 256) {
                float v = xg[i];
                v = fminf(fmaxf(v, -ACT_SCALE), ACT_SCALE);
                float q = fmaf(v, INV, MAGIC);
                int r = i / 17;
                int k = i - r * 17;
                s_iq[r * 32 + k] = (unsigned char)__float_as_int(q);
            }
        }
        __syncthreads();

        const float G1 = __ldg(&gG[0]);
        const float G2 = __ldg(&gG[1]);
        const float G3 = __ldg(&gG[2]);

        const int r0 = warp * 16 + g;

        uint32_t A1[4];
        {
            const unsigned char* p0 = s_iq + r0 * 32;
            const unsigned char* p1 = s_iq + (r0 + 8) * 32;
            A1[0] = *(const uint32_t*)(p0 + 4 * t);
            A1[1] = *(const uint32_t*)(p1 + 4 * t);
            A1[2] = *(const uint32_t*)(p0 + 16 + 4 * t);
            A1[3] = *(const uint32_t*)(p1 + 16 + 4 * t);
        }

        const float2* sb1v = (const float2*)sb1;
        const float2* sb2v = (const float2*)sb2;

        uint32_t A2[8];
#pragma unroll
        for (int m = 0; m < 4; ++m) {
            int C[2][4] = {{0, 0, 0, 0}, {0, 0, 0, 0}};
            uint4 w = *(const uint4*)&sW1[(m << 7) + (lane << 2)];
            IMMA16832(C[0], A1, w.x, w.y);
            IMMA16832(C[1], A1, w.z, w.w);
            const float2 bA = sb1v[(2 * m) * 4 + t];
            const float2 bB = sb1v[(2 * m + 1) * 4 + t];
            int pl0 = __byte_perm(requant_magic(C[0][0], G1, bA.x),
                                  requant_magic(C[0][1], G1, bA.y), 0x0040);
            int ph0 = __byte_perm(requant_magic(C[0][2], G1, bA.x),
                                  requant_magic(C[0][3], G1, bA.y), 0x0040);
            int pl1 = __byte_perm(requant_magic(C[1][0], G1, bB.x),
                                  requant_magic(C[1][1], G1, bB.y), 0x0040);
            int ph1 = __byte_perm(requant_magic(C[1][2], G1, bB.x),
                                  requant_magic(C[1][3], G1, bB.y), 0x0040);
            A2[2 * m]     = __byte_perm(pl0, pl1, 0x5410);
            A2[2 * m + 1] = __byte_perm(ph0, ph1, 0x5410);
        }

        uint32_t A3[8];
#pragma unroll
        for (int m = 0; m < 4; ++m) {
            int C[2][4] = {{0, 0, 0, 0}, {0, 0, 0, 0}};
#pragma unroll
            for (int kt = 0; kt < 2; ++kt) {
                uint4 w = *(const uint4*)&sW2[((kt * 4 + m) << 7) + (lane << 2)];
                IMMA16832(C[0], (A2 + 4 * kt), w.x, w.y);
                IMMA16832(C[1], (A2 + 4 * kt), w.z, w.w);
            }
            const float2 bA = sb2v[(2 * m) * 4 + t];
            const float2 bB = sb2v[(2 * m + 1) * 4 + t];
            int pl0 = __byte_perm(requant_magic(C[0][0], G2, bA.x),
                                  requant_magic(C[0][1], G2, bA.y), 0x0040);
            int ph0 = __byte_perm(requant_magic(C[0][2], G2, bA.x),
                                  requant_magic(C[0][3], G2, bA.y), 0x0040);
            int pl1 = __byte_perm(requant_magic(C[1][0], G2, bB.x),
                                  requant_magic(C[1][1], G2, bB.y), 0x0040);
            int ph1 = __byte_perm(requant_magic(C[1][2], G2, bB.x),
                                  requant_magic(C[1][3], G2, bB.y), 0x0040);
            A3[2 * m]     = __byte_perm(pl0, pl1, 0x5410);
            A3[2 * m + 1] = __byte_perm(ph0, ph1, 0x5410);
        }

        int D[4] = {0, 0, 0, 0};
        {
            uint4 w = *(const uint4*)&sW3[lane << 2];
            IMMA16832(D, (A3 + 0), w.x, w.y);
            IMMA16832(D, (A3 + 4), w.z, w.w);
        }

        if (t < 3) {
            const float2 b3p = *(const float2*)&sb3[2 * t];
            const int gr0 = rowbase + r0;
            const int gr1 = gr0 + 8;
            if (gr0 < B) {
                float2 o;
                o.x = fmaf((float)D[0], G3, b3p.x);
                o.y = fmaf((float)D[1], G3, b3p.y);
                *(float2*)&out[(size_t)gr0 * 6 + 2 * t] = o;
            }
            if (gr1 < B) {
                float2 o;
                o.x = fmaf((float)D[2], G3, b3p.x);
                o.y = fmaf((float)D[3], G3, b3p.y);
                *(float2*)&out[(size_t)gr1 * 6 + 2 * t] = o;
            }
        }
    } else {
        // ================= DP4A path (R2-proven) =================
        const int base = grp * 768 + 512;
        if (base >= B) return;
        const int rows = min(256, B - base);

        for (int i = tid; i < 1280; i += 256) ((int*)s_dq)[i] = 0;
        __syncthreads();
        {
            const float* xg = x + (size_t)base * 17;
            const int n = rows * 17;
            for (int i = tid; i < n; i += 256) {
                float v = xg[i];
                v = fminf(fmaxf(v, -ACT_SCALE), ACT_SCALE);
                int q = __float2int_rn(v * INV);
                int r = i / 17;
                int k = i - r * 17;
                s_dq[r * 20 + k] = (unsigned char)q;
            }
        }
        __syncthreads();

        if (tid < rows) {
            const float G1 = cQ.G1, G2 = cQ.G2, G3 = cQ.G3;

            int p0[5];
            {
                const int* rp = (const int*)(s_dq + tid * 20);
#pragma unroll
                for (int g = 0; g < 5; ++g) p0[g] = rp[g];
            }

            int a1[16];
#pragma unroll
            for (int jw = 0; jw < 16; ++jw) {
                const float4 bb = *(const float4*)&cQ.b1s[jw * 4];
                const float bj[4] = {bb.x, bb.y, bb.z, bb.w};
                int q[4];
#pragma unroll
                for (int jj = 0; jj < 4; ++jj) {
                    const int j = jw * 4 + jj;
                    int acc = 0;
#pragma unroll
                    for (int g = 0; g < 5; ++g)
                        acc = __dp4a(p0[g], cQ.W1[j * 5 + g], acc);
                    float f = fmaf((float)acc, G1, bj[jj]);
                    int qi = __float2int_rn(f);
                    q[jj] = min(max(qi, -127), 127);
                }
                a1[jw] = packq(q[0], q[1], q[2], q[3]);
            }

            int acc3[6] = {0, 0, 0, 0, 0, 0};
#pragma unroll
            for (int jw = 0; jw < 16; ++jw) {
                const float4 bb = *(const float4*)&cQ.b2s[jw * 4];
                const float bj[4] = {bb.x, bb.y, bb.z, bb.w};
                int q[4];
#pragma unroll
                for (int jj = 0; jj < 4; ++jj) {
                    const int j = jw * 4 + jj;
                    int acc = 0;
#pragma unroll
                    for (int g = 0; g < 4; ++g) {
                        const int4 w = *(const int4*)&cQ.W2[j * 16 + g * 4];
                        acc = __dp4a(a1[g * 4 + 0], w.x, acc);
                        acc = __dp4a(a1[g * 4 + 1], w.y, acc);
                        acc = __dp4a(a1[g * 4 + 2], w.z, acc);
                        acc = __dp4a(a1[g * 4 + 3], w.w, acc);
                    }
                    float f = fmaf((float)acc, G2, bj[jj]);
                    int qi = __float2int_rn(f);
                    q[jj] = min(max(qi, -127), 127);
                }
                const int a2w = packq(q[0], q[1], q[2], q[3]);
#pragma unroll
                for (int k = 0; k < 6; ++k)
                    acc3[k] = __dp4a(a2w, cQ.W3[k * 16 + jw], acc3[k]);
            }

#pragma unroll
            for (int k = 0; k < 6; ++k)
                s_out[tid * 6 + k] = fmaf((float)acc3[k], G3, cQ.b3[k]);
        }
        __syncthreads();

        float* og = out + (size_t)base * 6;
        if (rows == 256) {
            float4* ov = (float4*)og;
            const float4* sv = (const float4*)s_out;
            for (int i = tid; i < 384; i += 256) ov[i] = sv[i];
        } else {
            const int nf = rows * 6;
            for (int i = tid; i < nf; i += 256) og[i] = s_out[i];
        }
    }
}

extern "C" void kernel_launch(void* const* d_in, const int* in_sizes, int n_in,
                              void* d_out, int out_size) {
    const float* x  = (const float*)d_in[0];
    const float* W1 = (const float*)d_in[1];
    const float* b1 = (const float*)d_in[2];
    const float* W2 = (const float*)d_in[3];
    const float* b2 = (const float*)d_in[4];
    const float* W3 = (const float*)d_in[5];
    const float* b3 = (const float*)d_in[6];
    float* out = (float*)d_out;

    const int B = in_sizes[0] / 17;
    const int groups = (B + 767) / 768;

    prep_kernel<<<1, 256>>>(W1, b1, W2, b2, W3, b3);

    void* gq_ptr = nullptr;
    cudaGetSymbolAddress(&gq_ptr, gQ);
    cudaMemcpyToSymbolAsync(cQ, gq_ptr, sizeof(QConst), 0,
                            cudaMemcpyDeviceToDevice, 0);

    mlp_hybrid<<<groups * 5, 256>>>(x, out, B);
}

// round 15
// speedup vs baseline: 1.1595x; 1.0177x over previous
#include <cuda_runtime.h>
#include <cstdint>

// ============================================================================
// QuantizedActorMLP hybrid v2: 2/3 rows on int8 IMMA (R13), 1/3 on DP4A (R2).
// Round 15: smem UNION between the two mutually-exclusive paths (23KB -> 11.4KB)
// + __launch_bounds__(256,6) to restore 6 CTAs/SM. Compute paths unchanged.
// Pattern period 5 blocks = [I(128) x4, D(256)] over 768 rows.
// ============================================================================

#define ACT_SCALE 1.33f
#define QMAXF     127.0f
#define MAGIC     12582912.0f   // 1.5 * 2^23

// -------------------- DP4A-path constants (R2 layout) --------------------
struct QConst {
    int   W1[64 * 5];
    int   W2[64 * 16];
    int   W3[6 * 16];
    float b1s[64];
    float b2s[64];
    float b3[8];
    float G1, G2, G3;
};
__device__   QConst gQ;
__constant__ QConst cQ;

// -------------------- IMMA-path globals (R13 layout) --------------------
__device__ float    gG[3];
__device__ uint32_t gW1f[4 * 128];
__device__ uint32_t gW2f[8 * 128];
__device__ uint32_t gW3f[128];
__device__ float    gB1p[64];
__device__ float    gB2p[64];
__device__ float    gB3[8];

__device__ __forceinline__ int packq(int q0, int q1, int q2, int q3) {
    return __byte_perm(__byte_perm(q0, q1, 0x0040),
                       __byte_perm(q2, q3, 0x0040), 0x5410);
}

#define IMMA16832(Cv, Av, b0, b1)                                             \
    asm volatile(                                                             \
        "mma.sync.aligned.m16n8k32.row.col.s32.s8.s8.s32 "                    \
        "{%0,%1,%2,%3}, {%4,%5,%6,%7}, {%8,%9}, {%0,%1,%2,%3};"               \
        : "+r"((Cv)[0]), "+r"((Cv)[1]), "+r"((Cv)[2]), "+r"((Cv)[3])          \
        : "r"((Av)[0]), "r"((Av)[1]), "r"((Av)[2]), "r"((Av)[3]),             \
          "r"(b0), "r"(b1))

__device__ __forceinline__ int requant_magic(int acc, float G, float b) {
    float f = fmaf((float)acc, G, b);
    f = fminf(f, QMAXF);
    f = fmaxf(f, -QMAXF);
    return __float_as_int(__fadd_rn(f, MAGIC));
}

__device__ __forceinline__ int qw_s8(float w, float s) {
    float r = rintf(w / s);
    r = fminf(fmaxf(r, -QMAXF), QMAXF);
    return ((int)r) & 0xFF;
}

__device__ __forceinline__ int permN(int nt, int n) {
    return 16 * (nt >> 1) + 4 * (n >> 1) + 2 * (nt & 1) + (n & 1);
}

// ============================================================================
// Prep: scales, quantize weights; bake BOTH the dp4a pack and IMMA fragments.
// ============================================================================
__global__ void prep_kernel(const float* __restrict__ W1, const float* __restrict__ b1,
                            const float* __restrict__ W2, const float* __restrict__ b2,
                            const float* __restrict__ W3, const float* __restrict__ b3) {
    __shared__ float red[256];
    __shared__ float sS[3];
    const int tid = threadIdx.x;
    const float* Ws[3]  = {W1, W2, W3};
    const int    nel[3] = {64 * 17, 64 * 64, 6 * 64};

    for (int t = 0; t < 3; ++t) {
        float m = 0.0f;
        for (int i = tid; i < nel[t]; i += 256) m = fmaxf(m, fabsf(Ws[t][i]));
        red[tid] = m; __syncthreads();
        for (int s = 128; s > 0; s >>= 1) {
            if (tid < s) red[tid] = fmaxf(red[tid], red[tid + s]);
            __syncthreads();
        }
        if (tid == 0) sS[t] = red[0] / QMAXF;
        __syncthreads();
    }
    const float s1 = sS[0], s2 = sS[1], s3 = sS[2];
    const float step = ACT_SCALE / QMAXF;
    if (tid == 0) {
        gQ.G1 = s1; gQ.G2 = s2; gQ.G3 = step * s3;
        gG[0] = s1; gG[1] = s2; gG[2] = step * s3;
    }
    if (tid < 64) {
        gQ.b1s[tid] = b1[tid] / step;
        gQ.b2s[tid] = b2[tid] / step;
        int nt = tid >> 3, t = (tid >> 1) & 3, j = tid & 1;
        int l = 16 * (nt >> 1) + 4 * t + 2 * (nt & 1) + j;
        gB1p[tid] = b1[l] / step;
        gB2p[tid] = b2[l] / step;
    }
    if (tid < 8) {
        float v = (tid < 6) ? b3[tid] : 0.0f;
        gQ.b3[tid] = v; gB3[tid] = v;
    }

    // ---- dp4a pack (R2) ----
    for (int w = tid; w < 64 * 5; w += 256) {
        int j = w / 5, g = w % 5;
        int q[4];
#pragma unroll
        for (int b = 0; b < 4; ++b) {
            int k = 4 * g + b;
            int v = 0;
            if (k < 17) {
                float r = rintf(W1[j * 17 + k] / s1);
                v = (int)fminf(fmaxf(r, -QMAXF), QMAXF);
            }
            q[b] = v;
        }
        gQ.W1[w] = packq(q[0], q[1], q[2], q[3]);
    }
    for (int w = tid; w < 64 * 16; w += 256) {
        int j = w / 16, g = w % 16;
        int q[4];
#pragma unroll
        for (int b = 0; b < 4; ++b) {
            float r = rintf(W2[j * 64 + 4 * g + b] / s2);
            q[b] = (int)fminf(fmaxf(r, -QMAXF), QMAXF);
        }
        gQ.W2[w] = packq(q[0], q[1], q[2], q[3]);
    }
    for (int w = tid; w < 6 * 16; w += 256) {
        int k = w / 16, g = w % 16;
        int q[4];
#pragma unroll
        for (int b = 0; b < 4; ++b) {
            float r = rintf(W3[k * 64 + 4 * g + b] / s3);
            q[b] = (int)fminf(fmaxf(r, -QMAXF), QMAXF);
        }
        gQ.W3[w] = packq(q[0], q[1], q[2], q[3]);
    }

    // ---- IMMA fragments (R13) ----
    for (int idx = tid; idx < 4 * 128; idx += 256) {
        int m = idx >> 7, rem = idx & 127;
        int lane = rem >> 2, slot = rem & 3;
        int g = lane >> 2, t = lane & 3;
        int nt = 2 * m + (slot >> 1);
        int half = slot & 1;
        int n = permN(nt, g);
        int k0 = half * 16 + 4 * t;
        uint32_t word = 0;
#pragma unroll
        for (int i = 0; i < 4; ++i) {
            int k = k0 + i;
            int v = (k < 17) ? qw_s8(W1[n * 17 + k], s1) : 0;
            word |= (uint32_t)v << (8 * i);
        }
        gW1f[idx] = word;
    }
    for (int idx = tid; idx < 8 * 128; idx += 256) {
        int c = idx >> 7, rem = idx & 127;
        int lane = rem >> 2, slot = rem & 3;
        int g = lane >> 2, t = lane & 3;
        int kt = c >> 2, m = c & 3;
        int nt = 2 * m + (slot >> 1);
        int half = slot & 1;
        int n = permN(nt, g);
        int k0 = kt * 32 + half * 16 + 4 * t;
        uint32_t word = 0;
#pragma unroll
        for (int i = 0; i < 4; ++i)
            word |= (uint32_t)qw_s8(W2[(n << 6) + k0 + i], s2) << (8 * i);
        gW2f[idx] = word;
    }
    for (int idx = tid; idx < 128; idx += 256) {
        int lane = idx >> 2, slot = idx & 3;
        int g = lane >> 2, t = lane & 3;
        int kt = slot >> 1, half = slot & 1;
        int k0 = kt * 32 + half * 16 + 4 * t;
        uint32_t word = 0;
        if (g < 6) {
#pragma unroll
            for (int i = 0; i < 4; ++i)
                word |= (uint32_t)qw_s8(W3[(g << 6) + k0 + i], s3) << (8 * i);
        }
        gW3f[idx] = word;
    }
}

// ============================================================================
// Hybrid kernel with UNIONED smem. Pattern period 5 blocks = 768 rows.
//   IMMA layout:  iq@0(4096) W1@4096(2048) W2@6144(4096) W3@10240(512)
//                 b1@10752(256) b2@11008(256) b3@11264(32)
//   DP4A layout:  dq@0(5120) out@5120(6144)
// ============================================================================
#define SM_BYTES 11392

__global__ __launch_bounds__(256, 6) void mlp_hybrid(
    const float* __restrict__ x, float* __restrict__ out, int B) {

    __shared__ __align__(16) unsigned char sm[SM_BYTES];

    const int tid = threadIdx.x;
    const int pat = blockIdx.x % 5;
    const int grp = blockIdx.x / 5;
    const float INV = QMAXF / ACT_SCALE;

    if (pat < 4) {
        // ================= IMMA path (R13-proven) =================
        unsigned char* s_iq = sm;
        uint32_t* sW1 = (uint32_t*)(sm + 4096);
        uint32_t* sW2 = (uint32_t*)(sm + 6144);
        uint32_t* sW3 = (uint32_t*)(sm + 10240);
        float* sb1 = (float*)(sm + 10752);
        float* sb2 = (float*)(sm + 11008);
        float* sb3 = (float*)(sm + 11264);

        const int rowbase = grp * 768 + pat * 128;
        if (rowbase >= B) return;
        const int rows = min(128, B - rowbase);

        const int warp = tid >> 5;
        const int lane = tid & 31;
        const int g    = lane >> 2;
        const int t    = lane & 3;

        for (int i = tid; i < 4 * 128; i += 256) sW1[i] = gW1f[i];
        for (int i = tid; i < 8 * 128; i += 256) sW2[i] = gW2f[i];
        if (tid < 128) sW3[tid] = gW3f[tid];
        if (tid < 64) { sb1[tid] = gB1p[tid]; sb2[tid] = gB2p[tid]; }
        if (tid < 8)  sb3[tid] = gB3[tid];

        for (int i = tid; i < 1024; i += 256) ((uint32_t*)s_iq)[i] = 0u;
        __syncthreads();
        {
            const float* xg = x + (size_t)rowbase * 17;
            const int n = rows * 17;
            for (int i = tid; i < n; i += 256) {
                float v = xg[i];
                v = fminf(fmaxf(v, -ACT_SCALE), ACT_SCALE);
                float q = fmaf(v, INV, MAGIC);
                int r = i / 17;
                int k = i - r * 17;
                s_iq[r * 32 + k] = (unsigned char)__float_as_int(q);
            }
        }
        __syncthreads();

        const float G1 = __ldg(&gG[0]);
        const float G2 = __ldg(&gG[1]);
        const float G3 = __ldg(&gG[2]);

        const int r0 = warp * 16 + g;

        uint32_t A1[4];
        {
            const unsigned char* p0 = s_iq + r0 * 32;
            const unsigned char* p1 = s_iq + (r0 + 8) * 32;
            A1[0] = *(const uint32_t*)(p0 + 4 * t);
            A1[1] = *(const uint32_t*)(p1 + 4 * t);
            A1[2] = *(const uint32_t*)(p0 + 16 + 4 * t);
            A1[3] = *(const uint32_t*)(p1 + 16 + 4 * t);
        }

        const float2* sb1v = (const float2*)sb1;
        const float2* sb2v = (const float2*)sb2;

        uint32_t A2[8];
#pragma unroll
        for (int m = 0; m < 4; ++m) {
            int C[2][4] = {{0, 0, 0, 0}, {0, 0, 0, 0}};
            uint4 w = *(const uint4*)&sW1[(m << 7) + (lane << 2)];
            IMMA16832(C[0], A1, w.x, w.y);
            IMMA16832(C[1], A1, w.z, w.w);
            const float2 bA = sb1v[(2 * m) * 4 + t];
            const float2 bB = sb1v[(2 * m + 1) * 4 + t];
            int pl0 = __byte_perm(requant_magic(C[0][0], G1, bA.x),
                                  requant_magic(C[0][1], G1, bA.y), 0x0040);
            int ph0 = __byte_perm(requant_magic(C[0][2], G1, bA.x),
                                  requant_magic(C[0][3], G1, bA.y), 0x0040);
            int pl1 = __byte_perm(requant_magic(C[1][0], G1, bB.x),
                                  requant_magic(C[1][1], G1, bB.y), 0x0040);
            int ph1 = __byte_perm(requant_magic(C[1][2], G1, bB.x),
                                  requant_magic(C[1][3], G1, bB.y), 0x0040);
            A2[2 * m]     = __byte_perm(pl0, pl1, 0x5410);
            A2[2 * m + 1] = __byte_perm(ph0, ph1, 0x5410);
        }

        uint32_t A3[8];
#pragma unroll
        for (int m = 0; m < 4; ++m) {
            int C[2][4] = {{0, 0, 0, 0}, {0, 0, 0, 0}};
#pragma unroll
            for (int kt = 0; kt < 2; ++kt) {
                uint4 w = *(const uint4*)&sW2[((kt * 4 + m) << 7) + (lane << 2)];
                IMMA16832(C[0], (A2 + 4 * kt), w.x, w.y);
                IMMA16832(C[1], (A2 + 4 * kt), w.z, w.w);
            }
            const float2 bA = sb2v[(2 * m) * 4 + t];
            const float2 bB = sb2v[(2 * m + 1) * 4 + t];
            int pl0 = __byte_perm(requant_magic(C[0][0], G2, bA.x),
                                  requant_magic(C[0][1], G2, bA.y), 0x0040);
            int ph0 = __byte_perm(requant_magic(C[0][2], G2, bA.x),
                                  requant_magic(C[0][3], G2, bA.y), 0x0040);
            int pl1 = __byte_perm(requant_magic(C[1][0], G2, bB.x),
                                  requant_magic(C[1][1], G2, bB.y), 0x0040);
            int ph1 = __byte_perm(requant_magic(C[1][2], G2, bB.x),
                                  requant_magic(C[1][3], G2, bB.y), 0x0040);
            A3[2 * m]     = __byte_perm(pl0, pl1, 0x5410);
            A3[2 * m + 1] = __byte_perm(ph0, ph1, 0x5410);
        }

        int D[4] = {0, 0, 0, 0};
        {
            uint4 w = *(const uint4*)&sW3[lane << 2];
            IMMA16832(D, (A3 + 0), w.x, w.y);
            IMMA16832(D, (A3 + 4), w.z, w.w);
        }

        if (t < 3) {
            const float2 b3p = *(const float2*)&sb3[2 * t];
            const int gr0 = rowbase + r0;
            const int gr1 = gr0 + 8;
            if (gr0 < B) {
                float2 o;
                o.x = fmaf((float)D[0], G3, b3p.x);
                o.y = fmaf((float)D[1], G3, b3p.y);
                *(float2*)&out[(size_t)gr0 * 6 + 2 * t] = o;
            }
            if (gr1 < B) {
                float2 o;
                o.x = fmaf((float)D[2], G3, b3p.x);
                o.y = fmaf((float)D[3], G3, b3p.y);
                *(float2*)&out[(size_t)gr1 * 6 + 2 * t] = o;
            }
        }
    } else {
        // ================= DP4A path (R2-proven) =================
        unsigned char* s_dq = sm;
        float* s_out = (float*)(sm + 5120);

        const int base = grp * 768 + 512;
        if (base >= B) return;
        const int rows = min(256, B - base);

        for (int i = tid; i < 1280; i += 256) ((int*)s_dq)[i] = 0;
        __syncthreads();
        {
            const float* xg = x + (size_t)base * 17;
            const int n = rows * 17;
            for (int i = tid; i < n; i += 256) {
                float v = xg[i];
                v = fminf(fmaxf(v, -ACT_SCALE), ACT_SCALE);
                int q = __float2int_rn(v * INV);
                int r = i / 17;
                int k = i - r * 17;
                s_dq[r * 20 + k] = (unsigned char)q;
            }
        }
        __syncthreads();

        if (tid < rows) {
            const float G1 = cQ.G1, G2 = cQ.G2, G3 = cQ.G3;

            int p0[5];
            {
                const int* rp = (const int*)(s_dq + tid * 20);
#pragma unroll
                for (int g = 0; g < 5; ++g) p0[g] = rp[g];
            }

            int a1[16];
#pragma unroll
            for (int jw = 0; jw < 16; ++jw) {
                const float4 bb = *(const float4*)&cQ.b1s[jw * 4];
                const float bj[4] = {bb.x, bb.y, bb.z, bb.w};
                int q[4];
#pragma unroll
                for (int jj = 0; jj < 4; ++jj) {
                    const int j = jw * 4 + jj;
                    int acc = 0;
#pragma unroll
                    for (int g = 0; g < 5; ++g)
                        acc = __dp4a(p0[g], cQ.W1[j * 5 + g], acc);
                    float f = fmaf((float)acc, G1, bj[jj]);
                    int qi = __float2int_rn(f);
                    q[jj] = min(max(qi, -127), 127);
                }
                a1[jw] = packq(q[0], q[1], q[2], q[3]);
            }

            int acc3[6] = {0, 0, 0, 0, 0, 0};
#pragma unroll
            for (int jw = 0; jw < 16; ++jw) {
                const float4 bb = *(const float4*)&cQ.b2s[jw * 4];
                const float bj[4] = {bb.x, bb.y, bb.z, bb.w};
                int q[4];
#pragma unroll
                for (int jj = 0; jj < 4; ++jj) {
                    const int j = jw * 4 + jj;
                    int acc = 0;
#pragma unroll
                    for (int g = 0; g < 4; ++g) {
                        const int4 w = *(const int4*)&cQ.W2[j * 16 + g * 4];
                        acc = __dp4a(a1[g * 4 + 0], w.x, acc);
                        acc = __dp4a(a1[g * 4 + 1], w.y, acc);
                        acc = __dp4a(a1[g * 4 + 2], w.z, acc);
                        acc = __dp4a(a1[g * 4 + 3], w.w, acc);
                    }
                    float f = fmaf((float)acc, G2, bj[jj]);
                    int qi = __float2int_rn(f);
                    q[jj] = min(max(qi, -127), 127);
                }
                const int a2w = packq(q[0], q[1], q[2], q[3]);
#pragma unroll
                for (int k = 0; k < 6; ++k)
                    acc3[k] = __dp4a(a2w, cQ.W3[k * 16 + jw], acc3[k]);
            }

#pragma unroll
            for (int k = 0; k < 6; ++k)
                s_out[tid * 6 + k] = fmaf((float)acc3[k], G3, cQ.b3[k]);
        }
        __syncthreads();

        float* og = out + (size_t)base * 6;
        if (rows == 256) {
            float4* ov = (float4*)og;
            const float4* sv = (const float4*)s_out;
            for (int i = tid; i < 384; i += 256) ov[i] = sv[i];
        } else {
            const int nf = rows * 6;
            for (int i = tid; i < nf; i += 256) og[i] = s_out[i];
        }
    }
}

extern "C" void kernel_launch(void* const* d_in, const int* in_sizes, int n_in,
                              void* d_out, int out_size) {
    const float* x  = (const float*)d_in[0];
    const float* W1 = (const float*)d_in[1];
    const float* b1 = (const float*)d_in[2];
    const float* W2 = (const float*)d_in[3];
    const float* b2 = (const float*)d_in[4];
    const float* W3 = (const float*)d_in[5];
    const float* b3 = (const float*)d_in[6];
    float* out = (float*)d_out;

    const int B = in_sizes[0] / 17;
    const int groups = (B + 767) / 768;

    prep_kernel<<<1, 256>>>(W1, b1, W2, b2, W3, b3);

    void* gq_ptr = nullptr;
    cudaGetSymbolAddress(&gq_ptr, gQ);
    cudaMemcpyToSymbolAsync(cQ, gq_ptr, sizeof(QConst), 0,
                            cudaMemcpyDeviceToDevice, 0);

    mlp_hybrid<<<groups * 5, 256>>>(x, out, B);
}